// round 8
// baseline (speedup 1.0000x reference)
#include <cuda_runtime.h>
#include <math.h>
#include <stdint.h>

typedef unsigned long long ull;

// Problem constants
#define B_    32
#define T_    128
#define V_    16000
#define E_    512
#define Z_    128
#define H_    1024
#define DIN_  640        // E+Z
#define ROWS_ 64         // 32 sample-pass rows + 32 teacher-forced rows
#define NBCL_ 500        // 16000/32 logits col tiles
#define NSPL_ 12         // GEMM K-splits (single-wave grids of 768)
#define TINYF 1.17549435e-38f

// Output layout (float32): [s_s (B*T)] [p_s (B*T*V)] [s_f (B*T)] [p_f (B*T*V)]
#define O_PS  4096
#define O_SF  65540096
#define O_PF  65544192

// ---------------- device scratch (static globals; no allocations) -------------
__device__ float d_A0T[(DIN_+H_)*ROWS_];    // [k][64r]; emb rows, z rows, h0^T
__device__ float d_h1T[H_*ROWS_];
__device__ float d_c0[ROWS_*H_];
__device__ float d_c1[ROWS_*H_];
__device__ float d_gp[NSPL_][ROWS_*4*H_];   // K-split gate partials
__device__ int   d_tok[B_];
__device__ float d_logits[ROWS_*V_];
__device__ float d_pmax[ROWS_*NBCL_];
__device__ float d_psum[ROWS_*NBCL_];
__device__ float d_amv [ROWS_*NBCL_];
__device__ int   d_ami [ROWS_*NBCL_];

// ---------------- f32x2 packed math helpers ------------------------------------
__device__ __forceinline__ ull pk2(float x){
  ull r; asm("mov.b64 %0,{%1,%1};" : "=l"(r) : "f"(x)); return r;
}
__device__ __forceinline__ void fma2(ull &d, ull a, ull b){
  asm("fma.rn.f32x2 %0, %1, %2, %0;" : "+l"(d) : "l"(a), "l"(b));
}
__device__ __forceinline__ float2 up2(ull v){
  float2 f; asm("mov.b64 {%0,%1},%2;" : "=f"(f.x), "=f"(f.y) : "l"(v)); return f;
}

// ---------------- cp.async helpers ---------------------------------------------
__device__ __forceinline__ unsigned su32(const void* p){
  return (unsigned)__cvta_generic_to_shared(p);
}
__device__ __forceinline__ void cpa16(unsigned s, const void* g){
  asm volatile("cp.async.ca.shared.global [%0], [%1], 16;" :: "r"(s), "l"(g));
}
__device__ __forceinline__ void cp_commit(){ asm volatile("cp.async.commit_group;"); }
__device__ __forceinline__ void cp_wait3(){ asm volatile("cp.async.wait_group 3;"); }
__device__ __forceinline__ void cp_wait2(){ asm volatile("cp.async.wait_group 2;"); }
__device__ __forceinline__ void cp_wait1(){ asm volatile("cp.async.wait_group 1;"); }
__device__ __forceinline__ void cp_wait0(){ asm volatile("cp.async.wait_group 0;"); }

// ---------------- XLA-exact tanh (Eigen-style rational) ------------------------
__device__ __forceinline__ float tanh_xla(float x){
  float ax = fabsf(x);
  if (ax < 0.0004f) return x;
  float xc = fminf(fmaxf(x, -7.90531110763549805f), 7.90531110763549805f);
  float x2 = xc*xc;
  float p = fmaf(x2, -2.76076847742355e-16f, 2.00018790482477e-13f);
  p = fmaf(x2, p, -8.60467152213735e-11f);
  p = fmaf(x2, p,  5.12229709037114e-08f);
  p = fmaf(x2, p,  1.48572235717979e-05f);
  p = fmaf(x2, p,  6.37261928875436e-04f);
  p = fmaf(x2, p,  4.89352455891786e-03f);
  p = xc * p;
  float q = fmaf(x2, 1.19825839466702e-06f, 1.18534705686654e-04f);
  q = fmaf(x2, q, 2.26843463243900e-03f);
  q = fmaf(x2, q, 4.89352518554385e-03f);
  return p / q;
}
__device__ __forceinline__ float sigmoid_(float x){ return 0.5f + 0.5f*tanh_xla(0.5f*x); }

// ---------------- threefry2x32 (JAX partitionable) ----------------------------
__device__ __forceinline__ void tf2x32(unsigned k0, unsigned k1, unsigned x0, unsigned x1,
                                       unsigned &o0, unsigned &o1){
  unsigned k2 = k0 ^ k1 ^ 0x1BD11BDAu;
  x0 += k0; x1 += k1;
#define TFR(r) { x0 += x1; x1 = (x1<<(r)) | (x1>>(32-(r))); x1 ^= x0; }
  TFR(13) TFR(15) TFR(26) TFR(6)
  x0 += k1; x1 += k2 + 1u;
  TFR(17) TFR(29) TFR(16) TFR(24)
  x0 += k2; x1 += k0 + 2u;
  TFR(13) TFR(15) TFR(26) TFR(6)
  x0 += k0; x1 += k1 + 3u;
  TFR(17) TFR(29) TFR(16) TFR(24)
  x0 += k1; x1 += k2 + 4u;
  TFR(13) TFR(15) TFR(26) TFR(6)
  x0 += k2; x1 += k0 + 5u;
#undef TFR
  o0 = x0; o1 = x1;
}
__device__ __forceinline__ unsigned pbits(unsigned k0, unsigned k1, unsigned j){
  unsigned o0, o1; tf2x32(k0, k1, 0u, j, o0, o1); return o0 ^ o1;
}
__device__ __forceinline__ float gumbel_from_bits(unsigned bits){
  float f = __uint_as_float((bits>>9) | 0x3f800000u) - 1.0f;
  float u = fmaxf(TINYF, f + TINYF);
  return -logf(-logf(u));
}

// ---------------- init ---------------------------------------------------------
__global__ void k_init(const float* __restrict__ z, const float* __restrict__ emb){
  int i = blockIdx.x*blockDim.x + threadIdx.x;
  if (i < ROWS_*H_){
    d_A0T[DIN_*ROWS_ + i] = 0.f;    // h0^T = 0
    d_h1T[i] = 0.f;
    d_c0[i] = 0.f; d_c1[i] = 0.f;
  }
  if (i < Z_*ROWS_){                // z rows of A0T (constant across steps)
    int zz = i >> 6, r = i & 63;
    d_A0T[(E_+zz)*ROWS_ + r] = z[(r&31)*Z_ + zz];
  }
  if (i < E_*ROWS_){                // initial emb gather: START token (=1)
    int k = i >> 6, r = i & 63;
    d_A0T[(size_t)k*ROWS_ + r] = emb[(size_t)E_ + k];
  }
  if (i < B_) d_tok[i] = 1;
}

// ---- K-split GEMM: [64 x K]^T-stored A @ [K x 4096] W, f32x2, cp.async --------
// grid = 64 col-tiles x NSPL_ (=768, single wave); variable chunks per split.
__global__ void __launch_bounds__(128) k_gemm(
    const float* __restrict__ A1, int alen1, const float* __restrict__ A2,
    const float* __restrict__ W1, int wlen1, const float* __restrict__ W2,
    int totchunks, float* __restrict__ gp)
{
  __shared__ float As[2][32*64];
  __shared__ float Ws[2][32*64];
  const int tid = threadIdx.x;
  const int ct = blockIdx.x & 63, sp = blockIdx.x >> 6;
  const int rg = tid >> 4, cg = tid & 15;
  const int base = totchunks / NSPL_, rem = totchunks % NSPL_;
  const int nch  = base + (sp < rem ? 1 : 0);
  const int kbeg = 32 * (base*sp + (sp < rem ? sp : rem));
  const int cbase = ct * 64;

  const unsigned sA0 = su32(&As[0][0]), sA1 = su32(&As[1][0]);
  const unsigned sW0 = su32(&Ws[0][0]), sW1 = su32(&Ws[1][0]);

#define ISSUE(sa, sw, K0) {                                                  \
    const float* ap = ((K0) < alen1) ? (A1 + (size_t)(K0)*64)                \
                                     : (A2 + (size_t)((K0)-alen1)*64);       \
    const float* wp = ((K0) < wlen1) ? (W1 + (size_t)(K0)*4096)              \
                                     : (W2 + (size_t)((K0)-wlen1)*4096);     \
    _Pragma("unroll")                                                        \
    for (int i=0;i<4;i++){                                                   \
      int f = i*128 + tid;                                                   \
      cpa16((sa) + f*16, ap + f*4);                                          \
      int kk = f >> 4, c4 = (f & 15) * 4;                                    \
      cpa16((sw) + f*16, wp + (size_t)kk*4096 + cbase + c4);                 \
    }                                                                        \
    cp_commit(); }

  ull acc[8][2];
#pragma unroll
  for (int j=0;j<8;j++){ acc[j][0]=0ull; acc[j][1]=0ull; }

  ISSUE(sA0, sW0, kbeg)
  if (nch > 1) ISSUE(sA1, sW1, kbeg+32)

  for (int ci = 0; ci < nch; ci++){
    if (ci+1 < nch) cp_wait1(); else cp_wait0();
    __syncthreads();
    const float* Ac = &As[ci&1][0];
    const float* Wc = &Ws[ci&1][0];
#pragma unroll
    for (int kk=0; kk<32; kk++){
      float4 a0 = *(const float4*)(Ac + kk*64 + rg*8);
      float4 a1 = *(const float4*)(Ac + kk*64 + rg*8 + 4);
      ulonglong2 w = *(const ulonglong2*)(Wc + kk*64 + cg*4);
      ull pa;
      pa = pk2(a0.x); fma2(acc[0][0],pa,w.x); fma2(acc[0][1],pa,w.y);
      pa = pk2(a0.y); fma2(acc[1][0],pa,w.x); fma2(acc[1][1],pa,w.y);
      pa = pk2(a0.z); fma2(acc[2][0],pa,w.x); fma2(acc[2][1],pa,w.y);
      pa = pk2(a0.w); fma2(acc[3][0],pa,w.x); fma2(acc[3][1],pa,w.y);
      pa = pk2(a1.x); fma2(acc[4][0],pa,w.x); fma2(acc[4][1],pa,w.y);
      pa = pk2(a1.y); fma2(acc[5][0],pa,w.x); fma2(acc[5][1],pa,w.y);
      pa = pk2(a1.z); fma2(acc[6][0],pa,w.x); fma2(acc[6][1],pa,w.y);
      pa = pk2(a1.w); fma2(acc[7][0],pa,w.x); fma2(acc[7][1],pa,w.y);
    }
    __syncthreads();
    if (ci+2 < nch){
      if ((ci&1)==0){ ISSUE(sA0, sW0, kbeg+(ci+2)*32) }
      else          { ISSUE(sA1, sW1, kbeg+(ci+2)*32) }
    }
  }

  float* op = gp + (size_t)sp*ROWS_*4096;
#pragma unroll
  for (int j=0;j<8;j++){
    int r = rg*8 + j;
    float2 p0 = up2(acc[j][0]), p1 = up2(acc[j][1]);
    *(float4*)(op + (size_t)r*4096 + cbase + cg*4) = make_float4(p0.x,p0.y,p1.x,p1.y);
  }
#undef ISSUE
}

// ---------------- bias + LSTM activation; writes h^T --------------------------
__global__ void __launch_bounds__(512) k_act(const float* __restrict__ b,
    float* __restrict__ c, float* __restrict__ hT)
{
  int idx = blockIdx.x*512 + threadIdx.x;      // 65536
  int h = idx & 1023, r = idx >> 10;
  size_t base = (size_t)r*4096;
  float gi = b[h], gf = b[1024+h], gg = b[2048+h], go = b[3072+h];
#pragma unroll
  for (int s = 0; s < NSPL_; s++){
    const float* g = d_gp[s] + base;
    gi += g[h]; gf += g[1024+h]; gg += g[2048+h]; go += g[3072+h];
  }
  float cv = c[(size_t)r*1024 + h];
  float cn = sigmoid_(gf)*cv + sigmoid_(gi)*tanh_xla(gg);
  c[(size_t)r*1024 + h] = cn;
  hT[(size_t)h*64 + r]  = sigmoid_(go)*tanh_xla(cn);
}

// ------- logits GEMM (4-stage cp.async) + softmax partials + Gumbel argmax -----
// grid 500 col-tiles of 32; block 128; per-thread 8 rows x 2 cols.
__global__ void __launch_bounds__(128) k_logits(int t,
     const float* __restrict__ W, const float* __restrict__ bout)
{
  __shared__ float As[4][32*64];   // 32 KB
  __shared__ float Ws[4][32*32];   // 16 KB
  const int tid = threadIdx.x, cb = blockIdx.x;
  const int rg = tid >> 4, cg = tid & 15;
  const int cbase = cb * 32;

  unsigned sA[4], sW[4];
#pragma unroll
  for (int i=0;i<4;i++){ sA[i] = su32(&As[i][0]); sW[i] = su32(&Ws[i][0]); }

#define LISSUE(st, K0) {                                                     \
    const float* ap = d_h1T + (size_t)(K0)*64;                               \
    _Pragma("unroll")                                                        \
    for (int i=0;i<4;i++){ int f = i*128 + tid; cpa16(sA[st]+f*16, ap + f*4); } \
    _Pragma("unroll")                                                        \
    for (int i=0;i<2;i++){                                                   \
      int f = i*128 + tid, kk = f >> 3, c4 = (f & 7) * 4;                    \
      cpa16(sW[st]+f*16, W + (size_t)((K0)+kk)*V_ + cbase + c4);             \
    }                                                                        \
    cp_commit(); }

  ull acc[8];
#pragma unroll
  for (int j=0;j<8;j++) acc[j]=0ull;

  LISSUE(0, 0) LISSUE(1, 32) LISSUE(2, 64) LISSUE(3, 96)

  for (int ci=0; ci<32; ci++){
    if      (ci < 29) cp_wait3();
    else if (ci == 29) cp_wait2();
    else if (ci == 30) cp_wait1();
    else               cp_wait0();
    __syncthreads();
    const float* Ac = &As[ci&3][0];
    const float* Wc = &Ws[ci&3][0];
#pragma unroll
    for (int kk=0; kk<32; kk++){
      float4 a0 = *(const float4*)(Ac + kk*64 + rg*8);
      float4 a1 = *(const float4*)(Ac + kk*64 + rg*8 + 4);
      ull w = *(const ull*)(Wc + kk*32 + cg*2);
      fma2(acc[0], pk2(a0.x), w);
      fma2(acc[1], pk2(a0.y), w);
      fma2(acc[2], pk2(a0.z), w);
      fma2(acc[3], pk2(a0.w), w);
      fma2(acc[4], pk2(a1.x), w);
      fma2(acc[5], pk2(a1.y), w);
      fma2(acc[6], pk2(a1.z), w);
      fma2(acc[7], pk2(a1.w), w);
    }
    __syncthreads();
    if (ci+4 < 32){ int st = ci & 3; LISSUE(st, (ci+4)*32) }
  }
#undef LISSUE

  // RNG keys for both passes (stream 0 = free-running rows 0-31, 1 = teacher)
  unsigned k0p[2], k1p[2];
  { unsigned a0,a1; tf2x32(0u,42u,0u,0u,a0,a1); tf2x32(a0,a1,0u,(unsigned)t,k0p[0],k1p[0]); }
  { unsigned a0,a1; tf2x32(0u,42u,0u,1u,a0,a1); tf2x32(a0,a1,0u,(unsigned)t,k0p[1],k1p[1]); }

  float2 bo = *(const float2*)(bout + cbase + cg*2);
  const int c0 = cbase + cg*2, c1 = c0 + 1;
#pragma unroll
  for (int j=0;j<8;j++){
    int row = rg*8 + j;
    int pass = row >> 5, bb = row & 31;
    float2 p = up2(acc[j]);
    float v0 = p.x + bo.x, v1 = p.y + bo.y;
    float m = fmaxf(v0, v1);
#pragma unroll
    for (int msk=8; msk>=1; msk>>=1) m = fmaxf(m, __shfl_xor_sync(0xffffffffu, m, msk));
    float s = __expf(v0-m) + __expf(v1-m);
#pragma unroll
    for (int msk=8; msk>=1; msk>>=1) s += __shfl_xor_sync(0xffffffffu, s, msk);
    float g0 = gumbel_from_bits(pbits(k0p[pass], k1p[pass], (unsigned)(bb*V_ + c0)));
    float g1 = gumbel_from_bits(pbits(k0p[pass], k1p[pass], (unsigned)(bb*V_ + c1)));
    float t0 = v0 + g0, t1 = v1 + g1;
    float bv = t0; int bi = c0;
    if (t1 > bv){ bv = t1; bi = c1; }
#pragma unroll
    for (int msk=8; msk>=1; msk>>=1){
      float ov = __shfl_xor_sync(0xffffffffu, bv, msk);
      int   oi = __shfl_xor_sync(0xffffffffu, bi, msk);
      if (ov > bv || (ov == bv && oi < bi)){ bv = ov; bi = oi; }
    }
    *(float2*)&d_logits[(size_t)row*V_ + c0] = make_float2(v0,v1);
    if (cg == 0){
      d_pmax[row*NBCL_+cb] = m; d_psum[row*NBCL_+cb] = s;
      d_amv [row*NBCL_+cb] = bv; d_ami [row*NBCL_+cb] = bi;
    }
  }
}

// ------- fused: row LSE (recomputed per block) + p write + argmax/token --------
// grid 250 tiles of 64 cols; block 256. Blocks 0..63 also do row argmax + token.
__global__ void __launch_bounds__(256) k_final(int t, const int* __restrict__ x,
    const float* __restrict__ emb, float* __restrict__ out)
{
  __shared__ float tmpM[4][ROWS_], tmpS[4][ROWS_];
  __shared__ float sM[ROWS_], sL[ROWS_];
  __shared__ float sv[256];
  __shared__ int   si[256];
  __shared__ int   stok;
  const int tid = threadIdx.x, cb = blockIdx.x;

  // Phase A: per-row log-sum-exp over 500 tile partials (4 threads per row)
  {
    const int row = tid >> 2, part = tid & 3;
    const float* pm = d_pmax + (size_t)row*NBCL_;
    const float* ps = d_psum + (size_t)row*NBCL_;
    float m = -INFINITY;
    for (int j = part; j < NBCL_; j += 4) m = fmaxf(m, pm[j]);
    tmpM[part][row] = m;
    __syncthreads();
    float M = fmaxf(fmaxf(tmpM[0][row], tmpM[1][row]), fmaxf(tmpM[2][row], tmpM[3][row]));
    float s = 0.f;
    for (int j = part; j < NBCL_; j += 4) s += ps[j]*__expf(pm[j]-M);
    tmpS[part][row] = s;
    __syncthreads();
    if (part == 0){
      sM[row] = M;
      sL[row] = logf((tmpS[0][row]+tmpS[1][row]) + (tmpS[2][row]+tmpS[3][row]));
    }
    __syncthreads();
  }

  // Phase B: p = exp(logit - M - L) for this 64-col tile
  const int cbase = cb * 64;
#pragma unroll
  for (int i=0;i<4;i++){
    int e = i*256 + tid;
    int row = e >> 4, c4 = (e & 15) * 4;
    float ML = sM[row] + sL[row];
    float4 lg = *(const float4*)&d_logits[(size_t)row*V_ + cbase + c4];
    float4 pv = make_float4(__expf(lg.x-ML), __expf(lg.y-ML),
                            __expf(lg.z-ML), __expf(lg.w-ML));
    int pass = row>>5, b = row&31;
    size_t base = (pass==0) ? (size_t)O_PS + ((size_t)b*T_ + t)*V_
                            : (size_t)O_PF + ((size_t)b*T_ + t)*V_;
    *(float4*)&out[base + cbase + c4] = pv;
  }

  // Phase C (blocks 0..63): global argmax for row=cb, token update, emb gather
  if (cb < ROWS_){
    const int row = cb;
    float bv = -INFINITY; int bi = 0x7fffffff;
    for (int j=tid; j<NBCL_; j+=256){
      float v = d_amv[(size_t)row*NBCL_+j]; int ii = d_ami[(size_t)row*NBCL_+j];
      if (v > bv || (v == bv && ii < bi)){ bv = v; bi = ii; }
    }
    sv[tid] = bv; si[tid] = bi; __syncthreads();
    for (int k=128;k>0;k>>=1){
      if (tid<k){
        float ov = sv[tid+k]; int oi = si[tid+k];
        if (ov > sv[tid] || (ov == sv[tid] && oi < si[tid])){ sv[tid]=ov; si[tid]=oi; }
      }
      __syncthreads();
    }
    if (tid == 0){
      int idx = si[0];
      int pass = row>>5, b = row&31;
      if (pass == 0){ out[(size_t)b*T_ + t] = (float)idx; d_tok[b] = idx; stok = idx; }
      else          { out[(size_t)O_SF + (size_t)b*T_ + t] = (float)idx;
                      stok = x[(size_t)b*T_ + t]; }
    }
    __syncthreads();
    const int tok = stok;
    for (int k = tid; k < E_; k += 256)
      d_A0T[(size_t)k*ROWS_ + row] = emb[(size_t)tok*E_ + k];
  }
}

// ---------------- launch -------------------------------------------------------
extern "C" void kernel_launch(void* const* d_in, const int* in_sizes, int n_in,
                              void* d_out, int out_size)
{
  const int*   x    = (const int*)  d_in[0];
  const float* z    = (const float*)d_in[1];
  const float* emb  = (const float*)d_in[2];
  const float* Wx0  = (const float*)d_in[3];
  const float* Wh0  = (const float*)d_in[4];
  const float* b0   = (const float*)d_in[5];
  const float* Wx1  = (const float*)d_in[6];
  const float* Wh1  = (const float*)d_in[7];
  const float* b1   = (const float*)d_in[8];
  const float* Wout = (const float*)d_in[9];
  const float* bout = (const float*)d_in[10];
  float* out = (float*)d_out;

  float* pA0T; cudaGetSymbolAddress((void**)&pA0T, d_A0T);
  float* ph1T; cudaGetSymbolAddress((void**)&ph1T, d_h1T);
  float* pc0;  cudaGetSymbolAddress((void**)&pc0,  d_c0);
  float* pc1;  cudaGetSymbolAddress((void**)&pc1,  d_c1);
  float* pgp;  cudaGetSymbolAddress((void**)&pgp,  d_gp);

  k_init<<<256, 256>>>(z, emb);
  for (int t = 0; t < T_; t++){
    // LSTM0: K=1664 -> 52 chunks over 12 splits (single-wave grid 768)
    k_gemm<<<64*NSPL_, 128>>>(pA0T, 1<<30, (const float*)nullptr,
                              Wx0, DIN_, Wh0, 52, pgp);
    k_act <<<128, 512>>>(b0, pc0, pA0T + (size_t)DIN_*ROWS_);
    // LSTM1: K=2048 -> 64 chunks over 12 splits
    k_gemm<<<64*NSPL_, 128>>>(pA0T + (size_t)DIN_*ROWS_, H_, ph1T,
                              Wx1, H_, Wh1, 64, pgp);
    k_act <<<128, 512>>>(b1, pc1, ph1T);
    k_logits<<<NBCL_, 128>>>(t, Wout, bout);
    k_final<<<250, 256>>>(t, x, emb, out);
  }
}

// round 9
// speedup vs baseline: 1.0768x; 1.0768x over previous
#include <cuda_runtime.h>
#include <math.h>
#include <stdint.h>

typedef unsigned long long ull;

// Problem constants
#define B_    32
#define T_    128
#define V_    16000
#define E_    512
#define Z_    128
#define H_    1024
#define DIN_  640        // E+Z
#define ROWS_ 64         // 32 sample-pass rows + 32 teacher-forced rows
#define NBCL_ 500        // 16000/32 logits col tiles
#define TINYF 1.17549435e-38f

// Output layout (float32): [s_s (B*T)] [p_s (B*T*V)] [s_f (B*T)] [p_f (B*T*V)]
#define O_PS  4096
#define O_SF  65540096
#define O_PF  65544192

// ---------------- device scratch (static globals; no allocations) -------------
__device__ float d_A0T[(DIN_+H_)*ROWS_];    // [k][64r]; emb rows, z rows, h0^T
__device__ float d_h1T[H_*ROWS_];
__device__ float d_c0[ROWS_*H_];
__device__ float d_c1[ROWS_*H_];
__device__ float d_gp[16][ROWS_*4*H_];      // K-split gate partials
__device__ int   d_tok[B_];
__device__ float d_logits[ROWS_*V_];
__device__ float d_pmax[ROWS_*NBCL_];
__device__ float d_psum[ROWS_*NBCL_];
__device__ float d_rM[ROWS_];
__device__ float d_rL[ROWS_];
__device__ float d_amv [ROWS_*NBCL_];
__device__ int   d_ami [ROWS_*NBCL_];

// ---------------- f32x2 packed math helpers ------------------------------------
__device__ __forceinline__ ull pk2(float x){
  ull r; asm("mov.b64 %0,{%1,%1};" : "=l"(r) : "f"(x)); return r;
}
__device__ __forceinline__ void fma2(ull &d, ull a, ull b){
  asm("fma.rn.f32x2 %0, %1, %2, %0;" : "+l"(d) : "l"(a), "l"(b));
}
__device__ __forceinline__ float2 up2(ull v){
  float2 f; asm("mov.b64 {%0,%1},%2;" : "=f"(f.x), "=f"(f.y) : "l"(v)); return f;
}

// ---------------- cp.async helpers ---------------------------------------------
__device__ __forceinline__ unsigned su32(const void* p){
  return (unsigned)__cvta_generic_to_shared(p);
}
__device__ __forceinline__ void cpa16(unsigned s, const void* g){
  asm volatile("cp.async.ca.shared.global [%0], [%1], 16;" :: "r"(s), "l"(g));
}
__device__ __forceinline__ void cp_commit(){ asm volatile("cp.async.commit_group;"); }
__device__ __forceinline__ void cp_wait3(){ asm volatile("cp.async.wait_group 3;"); }
__device__ __forceinline__ void cp_wait2(){ asm volatile("cp.async.wait_group 2;"); }
__device__ __forceinline__ void cp_wait1(){ asm volatile("cp.async.wait_group 1;"); }
__device__ __forceinline__ void cp_wait0(){ asm volatile("cp.async.wait_group 0;"); }

// ---------------- XLA-exact tanh (Eigen-style rational) ------------------------
__device__ __forceinline__ float tanh_xla(float x){
  float ax = fabsf(x);
  if (ax < 0.0004f) return x;
  float xc = fminf(fmaxf(x, -7.90531110763549805f), 7.90531110763549805f);
  float x2 = xc*xc;
  float p = fmaf(x2, -2.76076847742355e-16f, 2.00018790482477e-13f);
  p = fmaf(x2, p, -8.60467152213735e-11f);
  p = fmaf(x2, p,  5.12229709037114e-08f);
  p = fmaf(x2, p,  1.48572235717979e-05f);
  p = fmaf(x2, p,  6.37261928875436e-04f);
  p = fmaf(x2, p,  4.89352455891786e-03f);
  p = xc * p;
  float q = fmaf(x2, 1.19825839466702e-06f, 1.18534705686654e-04f);
  q = fmaf(x2, q, 2.26843463243900e-03f);
  q = fmaf(x2, q, 4.89352518554385e-03f);
  return p / q;
}
__device__ __forceinline__ float sigmoid_(float x){ return 0.5f + 0.5f*tanh_xla(0.5f*x); }

// ---------------- threefry2x32 (JAX partitionable) ----------------------------
__device__ __forceinline__ void tf2x32(unsigned k0, unsigned k1, unsigned x0, unsigned x1,
                                       unsigned &o0, unsigned &o1){
  unsigned k2 = k0 ^ k1 ^ 0x1BD11BDAu;
  x0 += k0; x1 += k1;
#define TFR(r) { x0 += x1; x1 = (x1<<(r)) | (x1>>(32-(r))); x1 ^= x0; }
  TFR(13) TFR(15) TFR(26) TFR(6)
  x0 += k1; x1 += k2 + 1u;
  TFR(17) TFR(29) TFR(16) TFR(24)
  x0 += k2; x1 += k0 + 2u;
  TFR(13) TFR(15) TFR(26) TFR(6)
  x0 += k0; x1 += k1 + 3u;
  TFR(17) TFR(29) TFR(16) TFR(24)
  x0 += k1; x1 += k2 + 4u;
  TFR(13) TFR(15) TFR(26) TFR(6)
  x0 += k2; x1 += k0 + 5u;
#undef TFR
  o0 = x0; o1 = x1;
}
__device__ __forceinline__ unsigned pbits(unsigned k0, unsigned k1, unsigned j){
  unsigned o0, o1; tf2x32(k0, k1, 0u, j, o0, o1); return o0 ^ o1;
}
__device__ __forceinline__ float gumbel_from_bits(unsigned bits){
  float f = __uint_as_float((bits>>9) | 0x3f800000u) - 1.0f;
  float u = fmaxf(TINYF, f + TINYF);
  return -logf(-logf(u));
}

// ---------------- init ---------------------------------------------------------
__global__ void k_init(const float* __restrict__ z, const float* __restrict__ emb){
  int i = blockIdx.x*blockDim.x + threadIdx.x;
  if (i < ROWS_*H_){
    d_A0T[DIN_*ROWS_ + i] = 0.f;    // h0^T = 0
    d_h1T[i] = 0.f;
    d_c0[i] = 0.f; d_c1[i] = 0.f;
  }
  if (i < Z_*ROWS_){                // z rows of A0T (constant across steps)
    int zz = i >> 6, r = i & 63;
    d_A0T[(E_+zz)*ROWS_ + r] = z[(r&31)*Z_ + zz];
  }
  if (i < E_*ROWS_){                // initial emb gather: START token (=1)
    int k = i >> 6, r = i & 63;
    d_A0T[(size_t)k*ROWS_ + r] = emb[(size_t)E_ + k];
  }
  if (i < B_) d_tok[i] = 1;
}

// ---- K-split GEMM: [64 x K]^T-stored A @ [K x 4096] W, f32x2 ------------------
// grid = 32 col-tiles (128 cols) x NSPLIT; block 128; 4 uniform chunks of 32 k.
// Thread tile: 8 rows x 8 cols. Single-wave grids (<= 4 blocks/SM x 148).
__global__ void __launch_bounds__(128) k_gemm(
    const float* __restrict__ A1, int alen1, const float* __restrict__ A2,
    const float* __restrict__ W1, int wlen1, const float* __restrict__ W2,
    float* __restrict__ gp)
{
  __shared__ float As[2][32*64];    // 16 KB
  __shared__ float Ws[2][32*128];   // 32 KB
  const int tid = threadIdx.x;
  const int ct = blockIdx.x & 31, sp = blockIdx.x >> 5;
  const int rg = tid >> 4, cg = tid & 15;
  const int kbeg = sp * 128;
  const int cbase = ct * 128;

  const unsigned sA0 = su32(&As[0][0]), sA1 = su32(&As[1][0]);
  const unsigned sW0 = su32(&Ws[0][0]), sW1 = su32(&Ws[1][0]);

#define ISSUE(sa, sw, K0) {                                                  \
    const float* ap = ((K0) < alen1) ? (A1 + (size_t)(K0)*64)                \
                                     : (A2 + (size_t)((K0)-alen1)*64);       \
    const float* wp = ((K0) < wlen1) ? (W1 + (size_t)(K0)*4096)              \
                                     : (W2 + (size_t)((K0)-wlen1)*4096);     \
    _Pragma("unroll")                                                        \
    for (int i=0;i<4;i++){ int f = i*128 + tid; cpa16((sa)+f*16, ap + f*4); }\
    _Pragma("unroll")                                                        \
    for (int i=0;i<8;i++){                                                   \
      int f = i*128 + tid, kk = f >> 5, c4 = (f & 31) * 4;                   \
      cpa16((sw)+f*16, wp + (size_t)kk*4096 + cbase + c4);                   \
    }                                                                        \
    cp_commit(); }

  ull acc[8][4];
#pragma unroll
  for (int j=0;j<8;j++){ acc[j][0]=0ull; acc[j][1]=0ull; acc[j][2]=0ull; acc[j][3]=0ull; }

  ISSUE(sA0, sW0, kbeg)
  ISSUE(sA1, sW1, kbeg+32)

#pragma unroll
  for (int ci = 0; ci < 4; ci++){
    if (ci < 3) cp_wait1(); else cp_wait0();
    __syncthreads();
    const float* Ac = &As[ci&1][0];
    const float* Wc = &Ws[ci&1][0];
#pragma unroll
    for (int kk=0; kk<32; kk++){
      float4 a0 = *(const float4*)(Ac + kk*64 + rg*8);
      float4 a1 = *(const float4*)(Ac + kk*64 + rg*8 + 4);
      ulonglong2 w0 = *(const ulonglong2*)(Wc + kk*128 + cg*8);
      ulonglong2 w1 = *(const ulonglong2*)(Wc + kk*128 + cg*8 + 4);
      ull pa;
      pa = pk2(a0.x); fma2(acc[0][0],pa,w0.x); fma2(acc[0][1],pa,w0.y); fma2(acc[0][2],pa,w1.x); fma2(acc[0][3],pa,w1.y);
      pa = pk2(a0.y); fma2(acc[1][0],pa,w0.x); fma2(acc[1][1],pa,w0.y); fma2(acc[1][2],pa,w1.x); fma2(acc[1][3],pa,w1.y);
      pa = pk2(a0.z); fma2(acc[2][0],pa,w0.x); fma2(acc[2][1],pa,w0.y); fma2(acc[2][2],pa,w1.x); fma2(acc[2][3],pa,w1.y);
      pa = pk2(a0.w); fma2(acc[3][0],pa,w0.x); fma2(acc[3][1],pa,w0.y); fma2(acc[3][2],pa,w1.x); fma2(acc[3][3],pa,w1.y);
      pa = pk2(a1.x); fma2(acc[4][0],pa,w0.x); fma2(acc[4][1],pa,w0.y); fma2(acc[4][2],pa,w1.x); fma2(acc[4][3],pa,w1.y);
      pa = pk2(a1.y); fma2(acc[5][0],pa,w0.x); fma2(acc[5][1],pa,w0.y); fma2(acc[5][2],pa,w1.x); fma2(acc[5][3],pa,w1.y);
      pa = pk2(a1.z); fma2(acc[6][0],pa,w0.x); fma2(acc[6][1],pa,w0.y); fma2(acc[6][2],pa,w1.x); fma2(acc[6][3],pa,w1.y);
      pa = pk2(a1.w); fma2(acc[7][0],pa,w0.x); fma2(acc[7][1],pa,w0.y); fma2(acc[7][2],pa,w1.x); fma2(acc[7][3],pa,w1.y);
    }
    __syncthreads();
    if (ci+2 < 4){
      if ((ci&1)==0){ ISSUE(sA0, sW0, kbeg+(ci+2)*32) }
      else          { ISSUE(sA1, sW1, kbeg+(ci+2)*32) }
    }
  }

  float* op = gp + (size_t)sp*ROWS_*4096;
#pragma unroll
  for (int j=0;j<8;j++){
    int r = rg*8 + j;
    float2 p0 = up2(acc[j][0]), p1 = up2(acc[j][1]);
    float2 p2 = up2(acc[j][2]), p3 = up2(acc[j][3]);
    *(float4*)(op + (size_t)r*4096 + cbase + cg*8)     = make_float4(p0.x,p0.y,p1.x,p1.y);
    *(float4*)(op + (size_t)r*4096 + cbase + cg*8 + 4) = make_float4(p2.x,p2.y,p3.x,p3.y);
  }
#undef ISSUE
}

// ---------------- bias + LSTM activation; writes h^T --------------------------
__global__ void __launch_bounds__(512) k_act(int nsplit, const float* __restrict__ b,
    float* __restrict__ c, float* __restrict__ hT)
{
  int idx = blockIdx.x*512 + threadIdx.x;      // 65536
  int h = idx & 1023, r = idx >> 10;
  size_t base = (size_t)r*4096;
  float gi = b[h], gf = b[1024+h], gg = b[2048+h], go = b[3072+h];
  for (int s = 0; s < nsplit; s++){
    const float* g = d_gp[s] + base;
    gi += g[h]; gf += g[1024+h]; gg += g[2048+h]; go += g[3072+h];
  }
  float cv = c[(size_t)r*1024 + h];
  float cn = sigmoid_(gf)*cv + sigmoid_(gi)*tanh_xla(gg);
  c[(size_t)r*1024 + h] = cn;
  hT[(size_t)h*64 + r]  = sigmoid_(go)*tanh_xla(cn);
}

// ------- logits GEMM (4-stage cp.async) + softmax partials + Gumbel argmax -----
// grid 500 col-tiles of 32; block 128; per-thread 8 rows x 2 cols.
__global__ void __launch_bounds__(128) k_logits(int t,
     const float* __restrict__ W, const float* __restrict__ bout)
{
  __shared__ float As[4][32*64];   // 32 KB
  __shared__ float Ws[4][32*32];   // 16 KB
  const int tid = threadIdx.x, cb = blockIdx.x;
  const int rg = tid >> 4, cg = tid & 15;
  const int cbase = cb * 32;

  unsigned sA[4], sW[4];
#pragma unroll
  for (int i=0;i<4;i++){ sA[i] = su32(&As[i][0]); sW[i] = su32(&Ws[i][0]); }

#define LISSUE(st, K0) {                                                     \
    const float* ap = d_h1T + (size_t)(K0)*64;                               \
    _Pragma("unroll")                                                        \
    for (int i=0;i<4;i++){ int f = i*128 + tid; cpa16(sA[st]+f*16, ap + f*4); } \
    _Pragma("unroll")                                                        \
    for (int i=0;i<2;i++){                                                   \
      int f = i*128 + tid, kk = f >> 3, c4 = (f & 7) * 4;                    \
      cpa16(sW[st]+f*16, W + (size_t)((K0)+kk)*V_ + cbase + c4);             \
    }                                                                        \
    cp_commit(); }

  ull acc[8];
#pragma unroll
  for (int j=0;j<8;j++) acc[j]=0ull;

  LISSUE(0, 0) LISSUE(1, 32) LISSUE(2, 64) LISSUE(3, 96)

  for (int ci=0; ci<32; ci++){
    if      (ci < 29) cp_wait3();
    else if (ci == 29) cp_wait2();
    else if (ci == 30) cp_wait1();
    else               cp_wait0();
    __syncthreads();
    const float* Ac = &As[ci&3][0];
    const float* Wc = &Ws[ci&3][0];
#pragma unroll
    for (int kk=0; kk<32; kk++){
      float4 a0 = *(const float4*)(Ac + kk*64 + rg*8);
      float4 a1 = *(const float4*)(Ac + kk*64 + rg*8 + 4);
      ull w = *(const ull*)(Wc + kk*32 + cg*2);
      fma2(acc[0], pk2(a0.x), w);
      fma2(acc[1], pk2(a0.y), w);
      fma2(acc[2], pk2(a0.z), w);
      fma2(acc[3], pk2(a0.w), w);
      fma2(acc[4], pk2(a1.x), w);
      fma2(acc[5], pk2(a1.y), w);
      fma2(acc[6], pk2(a1.z), w);
      fma2(acc[7], pk2(a1.w), w);
    }
    __syncthreads();
    if (ci+4 < 32){ int st = ci & 3; LISSUE(st, (ci+4)*32) }
  }
#undef LISSUE

  // RNG keys for both passes (stream 0 = free-running rows 0-31, 1 = teacher)
  unsigned k0p[2], k1p[2];
  { unsigned a0,a1; tf2x32(0u,42u,0u,0u,a0,a1); tf2x32(a0,a1,0u,(unsigned)t,k0p[0],k1p[0]); }
  { unsigned a0,a1; tf2x32(0u,42u,0u,1u,a0,a1); tf2x32(a0,a1,0u,(unsigned)t,k0p[1],k1p[1]); }

  float2 bo = *(const float2*)(bout + cbase + cg*2);
  const int c0 = cbase + cg*2, c1 = c0 + 1;
#pragma unroll
  for (int j=0;j<8;j++){
    int row = rg*8 + j;
    int pass = row >> 5, bb = row & 31;
    float2 p = up2(acc[j]);
    float v0 = p.x + bo.x, v1 = p.y + bo.y;
    float m = fmaxf(v0, v1);
#pragma unroll
    for (int msk=8; msk>=1; msk>>=1) m = fmaxf(m, __shfl_xor_sync(0xffffffffu, m, msk));
    float s = __expf(v0-m) + __expf(v1-m);
#pragma unroll
    for (int msk=8; msk>=1; msk>>=1) s += __shfl_xor_sync(0xffffffffu, s, msk);
    float g0 = gumbel_from_bits(pbits(k0p[pass], k1p[pass], (unsigned)(bb*V_ + c0)));
    float g1 = gumbel_from_bits(pbits(k0p[pass], k1p[pass], (unsigned)(bb*V_ + c1)));
    float t0 = v0 + g0, t1 = v1 + g1;
    float bv = t0; int bi = c0;
    if (t1 > bv){ bv = t1; bi = c1; }
#pragma unroll
    for (int msk=8; msk>=1; msk>>=1){
      float ov = __shfl_xor_sync(0xffffffffu, bv, msk);
      int   oi = __shfl_xor_sync(0xffffffffu, bi, msk);
      if (ov > bv || (ov == bv && oi < bi)){ bv = ov; bi = oi; }
    }
    *(float2*)&d_logits[(size_t)row*V_ + c0] = make_float2(v0,v1);
    if (cg == 0){
      d_pmax[row*NBCL_+cb] = m; d_psum[row*NBCL_+cb] = s;
      d_amv [row*NBCL_+cb] = bv; d_ami [row*NBCL_+cb] = bi;
    }
  }
}

// -- per-row: LSE over 500 tiles, global argmax, token update, emb gather -------
__global__ void __launch_bounds__(256) k_argprep(int t, const int* __restrict__ x,
    const float* __restrict__ emb, float* __restrict__ out)
{
  __shared__ float sm[256], ss[256], sv[256];
  __shared__ int   si[256];
  __shared__ int   stok;
  const int row = blockIdx.x, tid = threadIdx.x;
  const float* pm = d_pmax + (size_t)row*NBCL_;
  const float* ps = d_psum + (size_t)row*NBCL_;

  float m = -INFINITY;
  for (int j=tid; j<NBCL_; j+=256) m = fmaxf(m, pm[j]);
  sm[tid] = m; __syncthreads();
  for (int k=128;k>0;k>>=1){ if (tid<k) sm[tid]=fmaxf(sm[tid],sm[tid+k]); __syncthreads(); }
  const float M = sm[0];
  float s = 0.f;
  for (int j=tid; j<NBCL_; j+=256) s += ps[j]*__expf(pm[j]-M);
  ss[tid] = s; __syncthreads();
  for (int k=128;k>0;k>>=1){ if (tid<k) ss[tid]+=ss[tid+k]; __syncthreads(); }
  if (tid == 0){ d_rM[row] = M; d_rL[row] = logf(ss[0]); }

  float bv = -INFINITY; int bi = 0x7fffffff;
  for (int j=tid; j<NBCL_; j+=256){
    float v = d_amv[(size_t)row*NBCL_+j]; int ii = d_ami[(size_t)row*NBCL_+j];
    if (v > bv || (v == bv && ii < bi)){ bv = v; bi = ii; }
  }
  sv[tid] = bv; si[tid] = bi; __syncthreads();
  for (int k=128;k>0;k>>=1){
    if (tid<k){
      float ov = sv[tid+k]; int oi = si[tid+k];
      if (ov > sv[tid] || (ov == sv[tid] && oi < si[tid])){ sv[tid]=ov; si[tid]=oi; }
    }
    __syncthreads();
  }
  if (tid == 0){
    int idx = si[0];
    int pass = row>>5, b = row&31;
    if (pass == 0){ out[(size_t)b*T_ + t] = (float)idx; d_tok[b] = idx; stok = idx; }
    else          { out[(size_t)O_SF + (size_t)b*T_ + t] = (float)idx;
                    stok = x[(size_t)b*T_ + t]; }
  }
  __syncthreads();
  const int tok = stok;
  for (int k = tid; k < E_; k += 256)
    d_A0T[(size_t)k*ROWS_ + row] = emb[(size_t)tok*E_ + k];
}

// ---------------- p = exp(logit - M - L) writer --------------------------------
// grid 250 tiles of 64 cols; block 256; 4 float4 per thread.
__global__ void __launch_bounds__(256) k_pwrite(int t, float* __restrict__ out)
{
  const int tid = threadIdx.x, cb = blockIdx.x;
  const int cbase = cb * 64;
#pragma unroll
  for (int i=0;i<4;i++){
    int e = i*256 + tid;
    int row = e >> 4, c4 = (e & 15) * 4;
    float ML = d_rM[row] + d_rL[row];
    float4 lg = *(const float4*)&d_logits[(size_t)row*V_ + cbase + c4];
    float4 pv = make_float4(__expf(lg.x-ML), __expf(lg.y-ML),
                            __expf(lg.z-ML), __expf(lg.w-ML));
    int pass = row>>5, b = row&31;
    size_t base = (pass==0) ? (size_t)O_PS + ((size_t)b*T_ + t)*V_
                            : (size_t)O_PF + ((size_t)b*T_ + t)*V_;
    *(float4*)&out[base + cbase + c4] = pv;
  }
}

// ---------------- launch -------------------------------------------------------
extern "C" void kernel_launch(void* const* d_in, const int* in_sizes, int n_in,
                              void* d_out, int out_size)
{
  const int*   x    = (const int*)  d_in[0];
  const float* z    = (const float*)d_in[1];
  const float* emb  = (const float*)d_in[2];
  const float* Wx0  = (const float*)d_in[3];
  const float* Wh0  = (const float*)d_in[4];
  const float* b0   = (const float*)d_in[5];
  const float* Wx1  = (const float*)d_in[6];
  const float* Wh1  = (const float*)d_in[7];
  const float* b1   = (const float*)d_in[8];
  const float* Wout = (const float*)d_in[9];
  const float* bout = (const float*)d_in[10];
  float* out = (float*)d_out;

  float* pA0T; cudaGetSymbolAddress((void**)&pA0T, d_A0T);
  float* ph1T; cudaGetSymbolAddress((void**)&ph1T, d_h1T);
  float* pc0;  cudaGetSymbolAddress((void**)&pc0,  d_c0);
  float* pc1;  cudaGetSymbolAddress((void**)&pc1,  d_c1);
  float* pgp;  cudaGetSymbolAddress((void**)&pgp,  d_gp);

  k_init<<<256, 256>>>(z, emb);
  for (int t = 0; t < T_; t++){
    // LSTM0: K=1664 = 13 splits x 128 (grid 32*13 = 416, single wave)
    k_gemm<<<32*13, 128>>>(pA0T, 1<<30, (const float*)nullptr,
                           Wx0, DIN_, Wh0, pgp);
    k_act <<<128, 512>>>(13, b0, pc0, pA0T + (size_t)DIN_*ROWS_);
    // LSTM1: K=2048 = 16 splits x 128 (grid 32*16 = 512, single wave)
    k_gemm<<<32*16, 128>>>(pA0T + (size_t)DIN_*ROWS_, H_, ph1T,
                           Wx1, H_, Wh1, pgp);
    k_act <<<128, 512>>>(16, b1, pc1, ph1T);
    k_logits<<<NBCL_, 128>>>(t, Wout, bout);
    k_argprep<<<ROWS_, 256>>>(t, x, emb, out);
    k_pwrite<<<250, 256>>>(t, out);
  }
}